// round 15
// baseline (speedup 1.0000x reference)
#include <cuda_runtime.h>
#include <cuda_bf16.h>
#include <math.h>

#define NB 8
#define H 256
#define W 256
#define H2 512
#define W2 512
#define HW (H*W)

// ---------------- scratch (device globals; no allocation) ----------------
__device__ unsigned short g_featsP[NB*16*HW]; // bf16 planar; ch 12..15 never written -> 0
__device__ unsigned short g_x1[NB*32*HW];     // conv1 out, bf16 planar
__device__ unsigned short g_x2[NB*64*HW];     // conv2 out, bf16 planar
__device__ float g_s1[32], g_bb1[32], g_s2[64], g_bb2[64]; // folded BN
// weights bf16, lane-packed per MMA fragment: uint4 = (a0,a1,a2,a3)
__device__ uint4 g_wt1[2*9*32];      // conv1: [m(2)][p(9)][lane]
__device__ uint4 g_wt2[4*9*2*32];    // conv2: [mt(4)][p(9)][cc(2)][lane]
__device__ uint4 g_wt3[4*32];        // conv3: [cc(4)][lane], co rows 8..15 zero

__device__ __forceinline__ unsigned int bf2(float lo, float hi) {
    unsigned int r; asm("cvt.rn.bf16x2.f32 %0, %1, %2;" : "=r"(r) : "f"(hi), "f"(lo)); return r;
}
__device__ __forceinline__ unsigned short bf1(float f) {
    unsigned short u; asm("cvt.rn.bf16.f32 %0, %1;" : "=h"(u) : "f"(f)); return u;
}

// ---------------- setup: BN fold + lane-packed bf16 weight preps ----------------
__global__ void k_setup(const float* __restrict__ w1, const float* __restrict__ w2,
                        const float* __restrict__ w3,
                        const float* __restrict__ g1, const float* __restrict__ b1,
                        const float* __restrict__ m1, const float* __restrict__ v1,
                        const float* __restrict__ g2, const float* __restrict__ b2,
                        const float* __restrict__ m2, const float* __restrict__ v2) {
    int idx = blockIdx.x * blockDim.x + threadIdx.x;
    if (idx < 32) { float s = g1[idx] * rsqrtf(v1[idx] + 1e-5f); g_s1[idx] = s; g_bb1[idx] = b1[idx] - m1[idx] * s; }
    else if (idx < 96) { int i = idx - 32; float s = g2[i] * rsqrtf(v2[i] + 1e-5f); g_s2[i] = s; g_bb2[i] = b2[i] - m2[i] * s; }

    int i1 = idx - 96;                       // conv1: 576 uint4
    if (i1 >= 0 && i1 < 576) {
        int lane = i1 & 31;
        int rest = i1 >> 5;
        int p = rest % 9, m = rest / 9;
        int g = lane >> 2, t4 = lane & 3;
        unsigned int v[4];
        #pragma unroll
        for (int j = 0; j < 4; j++) {
            int co = m*16 + g + (j & 1) * 8;
            int k0 = 2*t4 + (j >> 1) * 8;
            float lo = (k0   < 12) ? w1[(size_t)co*108 + k0*9 + p]     : 0.f;
            float hi = (k0+1 < 12) ? w1[(size_t)co*108 + (k0+1)*9 + p] : 0.f;
            v[j] = bf2(lo, hi);
        }
        g_wt1[i1] = make_uint4(v[0], v[1], v[2], v[3]);
    }
    int i2 = idx - 96 - 576;                 // conv2: 2304 uint4
    if (i2 >= 0 && i2 < 2304) {
        int lane = i2 & 31;
        int rest = i2 >> 5;
        int cc = rest & 1;
        int rest2 = rest >> 1;
        int p = rest2 % 9, mt = rest2 / 9;
        int g = lane >> 2, t4 = lane & 3;
        unsigned int v[4];
        #pragma unroll
        for (int j = 0; j < 4; j++) {
            int co = mt*16 + g + (j & 1) * 8;
            int ci = cc*16 + 2*t4 + (j >> 1) * 8;
            v[j] = bf2(w2[(size_t)co*288 + ci*9 + p], w2[(size_t)co*288 + (ci+1)*9 + p]);
        }
        g_wt2[i2] = make_uint4(v[0], v[1], v[2], v[3]);
    }
    int i3 = idx - 96 - 576 - 2304;          // conv3: 128 uint4
    if (i3 >= 0 && i3 < 128) {
        int lane = i3 & 31;
        int cc = i3 >> 5;
        int g = lane >> 2, t4 = lane & 3;
        unsigned int v[4];
        #pragma unroll
        for (int j = 0; j < 4; j++) {
            int co = g + (j & 1) * 8;         // rows 8..15 zero-padded
            int ci = cc*16 + 2*t4 + (j >> 1) * 8;
            v[j] = (co < 8) ? bf2(w3[(size_t)co*64 + ci], w3[(size_t)co*64 + ci + 1]) : 0u;
        }
        g_wt3[i3] = make_uint4(v[0], v[1], v[2], v[3]);
    }
}

// ---------------- fused preprocessing (writes bf16 planar features) ----------------
__device__ __forceinline__ float pool2(const float* row, int x2) {
    float2 a = *reinterpret_cast<const float2*>(row + x2);
    float2 b = *reinterpret_cast<const float2*>(row + x2 + W2);
    return 0.25f * (a.x + a.y + b.x + b.y);
}

__global__ void k_pre(const float* __restrict__ left, const float* __restrict__ right,
                      const float* __restrict__ normal, const float* __restrict__ disp) {
    int idx = blockIdx.x * blockDim.x + threadIdx.x;
    if (idx >= NB*3*HW) return;
    int x = idx & 255;
    int y = (idx >> 8) & 255;
    int nc = idx >> 16;
    int c = nc % 3, n = nc / 3;

    const float* rrow = right + ((size_t)(n*3 + c) * H2 + 2*y) * W2;
    const float* lrow = left  + ((size_t)(n*3 + c) * H2 + 2*y) * W2;
    float rv = pool2(rrow, 2*x);
    float l  = pool2(lrow, 2*x);

    size_t base = ((size_t)(n*16) * H + y) * W + x;
    g_featsP[base + (size_t)c * HW]     = bf1(normal[((size_t)(n*3 + c) * H + y) * W + x]);
    g_featsP[base + (size_t)(3+c) * HW] = bf1(l);
    g_featsP[base + (size_t)(6+c) * HW] = bf1(rv);

    float d = disp[((size_t)n * H + y) * W + x];
    float xs = (float)x - d;
    float x0f = floorf(xs);
    float frac = xs - x0f;
    int x0i = (int)x0f;
    int x1i = x0i + 1;
    float v0 = (x0i >= 0 && x0i < W) ? 1.f : 0.f;
    float v1 = (x1i >= 0 && x1i < W) ? 1.f : 0.f;
    int x0c = min(max(x0i, 0), W-1);
    int x1c = min(max(x1i, 0), W-1);
    float r0 = pool2(rrow, 2*x0c);
    float r1 = pool2(rrow, 2*x1c);
    float warped = (r0 * v0) * (1.f - frac) + (r1 * v1) * frac;
    g_featsP[base + (size_t)(9+c) * HW] = bf1(fabsf(l - warped));
}

// interleave two uint2 (4 bf16 each, same x-span, adjacent ci planes) into 4 bf16x2 words
__device__ __forceinline__ uint4 ilv(uint2 a, uint2 b) {
    uint4 o;
    o.x = __byte_perm(a.x, b.x, 0x5410);
    o.y = __byte_perm(a.x, b.x, 0x7632);
    o.z = __byte_perm(a.y, b.y, 0x5410);
    o.w = __byte_perm(a.y, b.y, 0x7632);
    return o;
}

// ================= conv1: 16(pad) -> 32, 3x3, pad 1, BN+ReLU — BF16 MMA =================
__global__ void __launch_bounds__(256, 3) k_conv1(const float* __restrict__ w_unused) {
    __shared__ unsigned int sB[4][8][136];
    int t = threadIdx.x;
    int warp = t >> 5, lane = t & 31;
    int nw = warp;
    int g = lane >> 2, t4 = lane & 3;

    int x0 = blockIdx.x * 128;
    int y0 = blockIdx.y * 2;
    int n  = blockIdx.z;

    float c[2][2][2][4];
    #pragma unroll
    for (int m = 0; m < 2; m++)
        #pragma unroll
        for (int r = 0; r < 2; r++)
            #pragma unroll
            for (int nt = 0; nt < 2; nt++) { c[m][r][nt][0]=0.f; c[m][r][nt][1]=0.f; c[m][r][nt][2]=0.f; c[m][r][nt][3]=0.f; }

    for (int i = t; i < 4*8*34; i += 256) {
        int row = i / 272; int rem = i - row*272;
        int j = rem / 34, xg = rem - j*34;
        int gy = y0 + row - 1, gx0 = x0 - 4 + xg*4;
        uint2 av = make_uint2(0u, 0u), bv = make_uint2(0u, 0u);
        if ((unsigned)gy < H && gx0 >= 0 && gx0 + 3 < W) {
            size_t o = (size_t)gy * W + gx0;
            av = *reinterpret_cast<const uint2*>(&g_featsP[((size_t)(n*16 + 2*j)) * HW + o]);
            bv = *reinterpret_cast<const uint2*>(&g_featsP[((size_t)(n*16 + 2*j + 1)) * HW + o]);
        }
        *reinterpret_cast<uint4*>(&sB[row][j][xg*4]) = ilv(av, bv);
    }
    __syncthreads();

    #pragma unroll
    for (int ky = 0; ky < 3; ky++) {
        #pragma unroll
        for (int kx = 0; kx < 3; kx++) {
            int p = ky*3 + kx;
            uint4 wa[2];
            #pragma unroll
            for (int m = 0; m < 2; m++)
                wa[m] = g_wt1[(m*9 + p)*32 + lane];
            #pragma unroll
            for (int r = 0; r < 2; r++) {
                const unsigned int* bb = &sB[ky + r][t4][nw*16 + g + kx + 3];
                #pragma unroll
                for (int nt = 0; nt < 2; nt++) {
                    unsigned int b0 = bb[nt*8];
                    unsigned int b1 = bb[nt*8 + 4*136];
                    #pragma unroll
                    for (int m = 0; m < 2; m++) {
                        asm volatile(
                            "mma.sync.aligned.m16n8k16.row.col.f32.bf16.bf16.f32 "
                            "{%0,%1,%2,%3}, {%4,%5,%6,%7}, {%8,%9}, {%0,%1,%2,%3};\n"
                            : "+f"(c[m][r][nt][0]), "+f"(c[m][r][nt][1]), "+f"(c[m][r][nt][2]), "+f"(c[m][r][nt][3])
                            : "r"(wa[m].x), "r"(wa[m].y), "r"(wa[m].z), "r"(wa[m].w), "r"(b0), "r"(b1));
                    }
                }
            }
        }
    }

    #pragma unroll
    for (int m = 0; m < 2; m++) {
        int co0 = m*16 + g;
        int co1 = co0 + 8;
        float s0 = g_s1[co0], bo0 = g_bb1[co0];
        float s1 = g_s1[co1], bo1 = g_bb1[co1];
        #pragma unroll
        for (int r = 0; r < 2; r++) {
            #pragma unroll
            for (int nt = 0; nt < 2; nt++) {
                int x = x0 + nw*16 + nt*8 + 2*t4;
                unsigned int o0 = bf2(fmaxf(fmaf(c[m][r][nt][0], s0, bo0), 0.f),
                                      fmaxf(fmaf(c[m][r][nt][1], s0, bo0), 0.f));
                unsigned int o1 = bf2(fmaxf(fmaf(c[m][r][nt][2], s1, bo1), 0.f),
                                      fmaxf(fmaf(c[m][r][nt][3], s1, bo1), 0.f));
                *reinterpret_cast<unsigned int*>(&g_x1[((size_t)(n*32 + co0) * H + y0 + r) * W + x]) = o0;
                *reinterpret_cast<unsigned int*>(&g_x1[((size_t)(n*32 + co1) * H + y0 + r) * W + x]) = o1;
            }
        }
    }
}

// ================= conv2: 32 -> 64, 3x3, pad 1, BN+ReLU — BF16 MMA, bf16 output =================
// Tile: 64 couts x 128 px x 2 rows. 2 M-groups (2 m-tiles each) x 4 N-warps x 32 px (nt=4).
// Per warp-pos: 16 MMAs for A=8wf + B=16wf -> 1.5 wf/MMA (was 2.0).
__global__ void __launch_bounds__(256, 2) k_conv2(const float* __restrict__ w_unused) {
    __shared__ unsigned int sB[4][16][136];   // 34.8 KB; pair stride 136 ≡ 8 (mod 32)
    int t = threadIdx.x;
    int warp = t >> 5, lane = t & 31;
    int mg = warp & 1;                 // M-group: couts mg*32 .. +31
    int nw = warp >> 1;                // 4 N-warps x 32 px
    int g = lane >> 2, t4 = lane & 3;

    int x0 = blockIdx.x * 128;
    int y0 = blockIdx.y * 2;
    int n  = blockIdx.z;

    float c[2][2][4][4];               // [m][row][nt][acc] = 64 regs
    #pragma unroll
    for (int m = 0; m < 2; m++)
        #pragma unroll
        for (int r = 0; r < 2; r++)
            #pragma unroll
            for (int nt = 0; nt < 4; nt++) { c[m][r][nt][0]=0.f; c[m][r][nt][1]=0.f; c[m][r][nt][2]=0.f; c[m][r][nt][3]=0.f; }

    // fill: 4 rows x 16 pairs x 34 uint4 groups
    for (int i = t; i < 4*16*34; i += 256) {
        int row = i / 544; int rem = i - row*544;
        int j = rem / 34, xg = rem - j*34;
        int gy = y0 + row - 1, gx0 = x0 - 4 + xg*4;
        uint2 av = make_uint2(0u, 0u), bv = make_uint2(0u, 0u);
        if ((unsigned)gy < H && gx0 >= 0 && gx0 + 3 < W) {
            size_t o = (size_t)gy * W + gx0;
            av = *reinterpret_cast<const uint2*>(&g_x1[((size_t)(n*32 + 2*j)) * HW + o]);
            bv = *reinterpret_cast<const uint2*>(&g_x1[((size_t)(n*32 + 2*j + 1)) * HW + o]);
        }
        *reinterpret_cast<uint4*>(&sB[row][j][xg*4]) = ilv(av, bv);
    }
    __syncthreads();

    #pragma unroll
    for (int cc = 0; cc < 2; cc++) {
        #pragma unroll
        for (int ky = 0; ky < 3; ky++) {
            #pragma unroll
            for (int kx = 0; kx < 3; kx++) {
                int p = ky*3 + kx;
                uint4 wa[2];
                #pragma unroll
                for (int m = 0; m < 2; m++)
                    wa[m] = g_wt2[(((mg*2 + m)*9 + p)*2 + cc)*32 + lane];
                #pragma unroll
                for (int r = 0; r < 2; r++) {
                    const unsigned int* bb = &sB[ky + r][cc*8 + t4][nw*32 + g + kx + 3];
                    #pragma unroll
                    for (int nt = 0; nt < 4; nt++) {
                        unsigned int b0 = bb[nt*8];
                        unsigned int b1 = bb[nt*8 + 4*136];   // pair +4 -> k+8
                        #pragma unroll
                        for (int m = 0; m < 2; m++) {
                            asm volatile(
                                "mma.sync.aligned.m16n8k16.row.col.f32.bf16.bf16.f32 "
                                "{%0,%1,%2,%3}, {%4,%5,%6,%7}, {%8,%9}, {%0,%1,%2,%3};\n"
                                : "+f"(c[m][r][nt][0]), "+f"(c[m][r][nt][1]), "+f"(c[m][r][nt][2]), "+f"(c[m][r][nt][3])
                                : "r"(wa[m].x), "r"(wa[m].y), "r"(wa[m].z), "r"(wa[m].w), "r"(b0), "r"(b1));
                        }
                    }
                }
            }
        }
    }

    #pragma unroll
    for (int m = 0; m < 2; m++) {
        int co0 = (mg*2 + m)*16 + g;
        int co1 = co0 + 8;
        float s0 = g_s2[co0], bo0 = g_bb2[co0];
        float s1 = g_s2[co1], bo1 = g_bb2[co1];
        #pragma unroll
        for (int r = 0; r < 2; r++) {
            #pragma unroll
            for (int nt = 0; nt < 4; nt++) {
                int x = x0 + nw*32 + nt*8 + 2*t4;
                unsigned int o0 = bf2(fmaxf(fmaf(c[m][r][nt][0], s0, bo0), 0.f),
                                      fmaxf(fmaf(c[m][r][nt][1], s0, bo0), 0.f));
                unsigned int o1 = bf2(fmaxf(fmaf(c[m][r][nt][2], s1, bo1), 0.f),
                                      fmaxf(fmaf(c[m][r][nt][3], s1, bo1), 0.f));
                *reinterpret_cast<unsigned int*>(&g_x2[((size_t)(n*64 + co0) * H + y0 + r) * W + x]) = o0;
                *reinterpret_cast<unsigned int*>(&g_x2[((size_t)(n*64 + co1) * H + y0 + r) * W + x]) = o1;
            }
        }
    }
}

// ======== fused tail: conv3 via BF16 MMA (M=16 couts pad, N=8 px, K=64) + softmax prop ========
__global__ void __launch_bounds__(256) k_tail(const float* __restrict__ disp,
                                              float* __restrict__ out) {
    __shared__ float sAff[8][18][72];   // 40.5 KB
    __shared__ float sD[18][72];        //  5.1 KB
    int t = threadIdx.x;
    int warp = t >> 5, lane = t & 31;
    int g = lane >> 2, t4 = lane & 3;
    int x0 = blockIdx.x * 64;
    int y0 = blockIdx.y * 16;
    int n  = blockIdx.z;

    uint4 wa[4];
    #pragma unroll
    for (int cc = 0; cc < 4; cc++) wa[cc] = g_wt3[cc*32 + lane];

    for (int task = t; task < 18*18; task += 256) {
        int yy = task / 18, jg = task - yy*18;
        int gy = y0 + yy - 1, gx0 = x0 - 4 + jg*4;
        float4 dv = make_float4(0.f, 0.f, 0.f, 0.f);
        if ((unsigned)gy < H && gx0 >= 0 && gx0 + 3 < W)
            dv = *reinterpret_cast<const float4*>(&disp[(size_t)n * HW + (size_t)gy * W + gx0]);
        *reinterpret_cast<float4*>(&sD[yy][jg*4]) = dv;
    }

    const unsigned short* xb = g_x2 + (size_t)(n*64) * HW;
    for (int grp = warp; grp < 162; grp += 8) {
        int yy = grp / 9, gi = grp - yy*9;
        int gy = y0 + yy - 1;
        int px = x0 - 4 + gi*8 + g;
        bool ok = ((unsigned)gy < H) && ((unsigned)px < W);
        size_t o = ok ? ((size_t)gy * W + px) : 0;
        const unsigned short* bp = xb + o;
        float c0 = 0.f, c1 = 0.f, c2 = 0.f, c3 = 0.f;
        #pragma unroll
        for (int cc = 0; cc < 4; cc++) {
            size_t ci0 = (size_t)(cc*16 + 2*t4) * HW;
            unsigned int u0 = ok ? (unsigned int)bp[ci0]          : 0u;
            unsigned int u1 = ok ? (unsigned int)bp[ci0 + HW]     : 0u;
            unsigned int u2 = ok ? (unsigned int)bp[ci0 + 8*HW]   : 0u;
            unsigned int u3 = ok ? (unsigned int)bp[ci0 + 9*HW]   : 0u;
            unsigned int b0 = u0 | (u1 << 16);
            unsigned int b1 = u2 | (u3 << 16);
            asm volatile(
                "mma.sync.aligned.m16n8k16.row.col.f32.bf16.bf16.f32 "
                "{%0,%1,%2,%3}, {%4,%5,%6,%7}, {%8,%9}, {%0,%1,%2,%3};\n"
                : "+f"(c0), "+f"(c1), "+f"(c2), "+f"(c3)
                : "r"(wa[cc].x), "r"(wa[cc].y), "r"(wa[cc].z), "r"(wa[cc].w), "r"(b0), "r"(b1));
        }
        sAff[g][yy][gi*8 + 2*t4]     = fmaxf(c0, 0.f);
        sAff[g][yy][gi*8 + 2*t4 + 1] = fmaxf(c1, 0.f);
    }
    __syncthreads();

    const int dy[8] = { 1, 1, 1, 0, 0, -1, -1, -1 };
    const int dx[8] = { 1, 0,-1, 1,-1,  1,  0, -1 };
    for (int o = t; o < 64*16; o += 256) {
        int oy = o >> 6, ox = o & 63;
        int yy = oy + 1, xx = ox + 4;
        float gg[8], dd[8];
        #pragma unroll
        for (int k = 0; k < 8; k++) {
            gg[k] = sAff[k][yy + dy[k]][xx + dx[k]];
            dd[k] = sD[yy + dy[k]][xx + dx[k]];
        }
        float m = gg[0];
        #pragma unroll
        for (int k = 1; k < 8; k++) m = fmaxf(m, gg[k]);
        float se = 0.f, sp = 0.f;
        #pragma unroll
        for (int k = 0; k < 8; k++) {
            float e = expf(gg[k] - m);
            se += e;
            sp = fmaf(e, dd[k], sp);
        }
        float prop = sp / se;
        out[(size_t)n * HW + (size_t)(y0 + oy) * W + x0 + ox] = 0.3f * prop + 0.7f * sD[yy][xx];
    }
}

// ---------------- launch ----------------
extern "C" void kernel_launch(void* const* d_in, const int* in_sizes, int n_in,
                              void* d_out, int out_size) {
    const float* normal = (const float*)d_in[0];
    const float* left   = (const float*)d_in[1];
    const float* right  = (const float*)d_in[2];
    const float* disp   = (const float*)d_in[3];
    const float* w1 = (const float*)d_in[4];
    const float* g1 = (const float*)d_in[5];
    const float* b1 = (const float*)d_in[6];
    const float* m1 = (const float*)d_in[7];
    const float* v1 = (const float*)d_in[8];
    const float* w2 = (const float*)d_in[9];
    const float* g2 = (const float*)d_in[10];
    const float* b2 = (const float*)d_in[11];
    const float* m2 = (const float*)d_in[12];
    const float* v2 = (const float*)d_in[13];
    const float* w3 = (const float*)d_in[14];
    float* out = (float*)d_out;

    k_setup<<<(96 + 576 + 2304 + 128 + 255) / 256, 256>>>(w1, w2, w3, g1, b1, m1, v1, g2, b2, m2, v2);

    k_pre<<<(NB*3*HW + 255) / 256, 256>>>(left, right, normal, disp);

    k_conv1<<<dim3(W/128, H/2, NB), 256>>>(w1);
    k_conv2<<<dim3(W/128, H/2, NB), 256>>>(w2);

    k_tail<<<dim3(W/64, H/16, NB), 256>>>(disp, out);
}

// round 17
// speedup vs baseline: 1.1994x; 1.1994x over previous
#include <cuda_runtime.h>
#include <cuda_bf16.h>
#include <math.h>

#define NB 8
#define H 256
#define W 256
#define H2 512
#define W2 512
#define HW (H*W)

// ---------------- scratch (device globals; no allocation) ----------------
__device__ unsigned short g_featsP[NB*16*HW]; // bf16 planar; ch 12..15 never written -> 0
__device__ unsigned short g_x1[NB*32*HW];     // conv1 out, bf16 planar
// conv2 out, pair-packed: uint word[n][chunk4][j8][y][x] = bf16x2(ch chunk*16+j, ch chunk*16+j+8)
__device__ unsigned int g_x2p[(size_t)NB*32*HW];
__device__ float g_s1[32], g_bb1[32], g_s2[64], g_bb2[64]; // folded BN
// weights bf16, lane-packed per MMA fragment: uint4 = (a0,a1,a2,a3)
__device__ uint4 g_wt1[2*9*32];      // conv1: [m(2)][p(9)][lane]
__device__ uint4 g_wt2[4*9*2*32];    // conv2: [mt(4)][p(9)][cc(2)][lane]
__device__ uint4 g_wt3[4*32];        // conv3: [cc(4)][lane], K permuted j<->(j,j+8)

__device__ __forceinline__ unsigned int bf2(float lo, float hi) {
    unsigned int r; asm("cvt.rn.bf16x2.f32 %0, %1, %2;" : "=r"(r) : "f"(hi), "f"(lo)); return r;
}
__device__ __forceinline__ unsigned short bf1(float f) {
    unsigned short u; asm("cvt.rn.bf16.f32 %0, %1;" : "=h"(u) : "f"(f)); return u;
}

__device__ __forceinline__ float pool2(const float* row, int x2) {
    float2 a = *reinterpret_cast<const float2*>(row + x2);
    float2 b = *reinterpret_cast<const float2*>(row + x2 + W2);
    return 0.25f * (a.x + a.y + b.x + b.y);
}

// ---------------- fused: preprocessing + BN fold + weight preps (ONE launch) ----------------
// blocks [0, 6144): feature preprocessing; blocks [6144, 6157): setup
__global__ void k_pre(const float* __restrict__ left, const float* __restrict__ right,
                      const float* __restrict__ normal, const float* __restrict__ disp,
                      const float* __restrict__ w1, const float* __restrict__ w2,
                      const float* __restrict__ w3,
                      const float* __restrict__ g1, const float* __restrict__ b1,
                      const float* __restrict__ m1, const float* __restrict__ v1,
                      const float* __restrict__ g2, const float* __restrict__ b2,
                      const float* __restrict__ m2, const float* __restrict__ v2) {
    if (blockIdx.x >= 6144) {
        int idx = (blockIdx.x - 6144) * blockDim.x + threadIdx.x;
        if (idx < 32) { float s = g1[idx] * rsqrtf(v1[idx] + 1e-5f); g_s1[idx] = s; g_bb1[idx] = b1[idx] - m1[idx] * s; }
        else if (idx < 96) { int i = idx - 32; float s = g2[i] * rsqrtf(v2[i] + 1e-5f); g_s2[i] = s; g_bb2[i] = b2[i] - m2[i] * s; }

        int i1 = idx - 96;                       // conv1: 576 uint4
        if (i1 >= 0 && i1 < 576) {
            int lane = i1 & 31;
            int rest = i1 >> 5;
            int p = rest % 9, m = rest / 9;
            int g = lane >> 2, t4 = lane & 3;
            unsigned int v[4];
            #pragma unroll
            for (int j = 0; j < 4; j++) {
                int co = m*16 + g + (j & 1) * 8;
                int k0 = 2*t4 + (j >> 1) * 8;
                float lo = (k0   < 12) ? w1[(size_t)co*108 + k0*9 + p]     : 0.f;
                float hi = (k0+1 < 12) ? w1[(size_t)co*108 + (k0+1)*9 + p] : 0.f;
                v[j] = bf2(lo, hi);
            }
            g_wt1[i1] = make_uint4(v[0], v[1], v[2], v[3]);
        }
        int i2 = idx - 96 - 576;                 // conv2: 2304 uint4
        if (i2 >= 0 && i2 < 2304) {
            int lane = i2 & 31;
            int rest = i2 >> 5;
            int cc = rest & 1;
            int rest2 = rest >> 1;
            int p = rest2 % 9, mt = rest2 / 9;
            int g = lane >> 2, t4 = lane & 3;
            unsigned int v[4];
            #pragma unroll
            for (int j = 0; j < 4; j++) {
                int co = mt*16 + g + (j & 1) * 8;
                int ci = cc*16 + 2*t4 + (j >> 1) * 8;
                v[j] = bf2(w2[(size_t)co*288 + ci*9 + p], w2[(size_t)co*288 + (ci+1)*9 + p]);
            }
            g_wt2[i2] = make_uint4(v[0], v[1], v[2], v[3]);
        }
        int i3 = idx - 96 - 576 - 2304;          // conv3: 128 uint4, K permuted pi(2j)=j, pi(2j+1)=j+8
        if (i3 >= 0 && i3 < 128) {
            int lane = i3 & 31;
            int cc = i3 >> 5;
            int g = lane >> 2, t4 = lane & 3;
            unsigned int v[4];
            // A fragment K-slots: a0: k=2t4,2t4+1 -> ch t4, t4+8 ; a2: k=2t4+8,2t4+9 -> ch t4+4, t4+12
            v[0] = (g < 8) ? bf2(w3[(size_t)g*64 + cc*16 + t4],     w3[(size_t)g*64 + cc*16 + t4 + 8])  : 0u;
            v[1] = 0u;   // co rows 8..15 zero
            v[2] = (g < 8) ? bf2(w3[(size_t)g*64 + cc*16 + t4 + 4], w3[(size_t)g*64 + cc*16 + t4 + 12]) : 0u;
            v[3] = 0u;
            g_wt3[i3] = make_uint4(v[0], v[1], v[2], v[3]);
        }
        return;
    }

    int idx = blockIdx.x * blockDim.x + threadIdx.x;
    int x = idx & 255;
    int y = (idx >> 8) & 255;
    int nc = idx >> 16;
    int c = nc % 3, n = nc / 3;

    const float* rrow = right + ((size_t)(n*3 + c) * H2 + 2*y) * W2;
    const float* lrow = left  + ((size_t)(n*3 + c) * H2 + 2*y) * W2;
    float rv = pool2(rrow, 2*x);
    float l  = pool2(lrow, 2*x);

    size_t base = ((size_t)(n*16) * H + y) * W + x;
    g_featsP[base + (size_t)c * HW]     = bf1(normal[((size_t)(n*3 + c) * H + y) * W + x]);
    g_featsP[base + (size_t)(3+c) * HW] = bf1(l);
    g_featsP[base + (size_t)(6+c) * HW] = bf1(rv);

    float d = disp[((size_t)n * H + y) * W + x];
    float xs = (float)x - d;
    float x0f = floorf(xs);
    float frac = xs - x0f;
    int x0i = (int)x0f;
    int x1i = x0i + 1;
    float vv0 = (x0i >= 0 && x0i < W) ? 1.f : 0.f;
    float vv1 = (x1i >= 0 && x1i < W) ? 1.f : 0.f;
    int x0c = min(max(x0i, 0), W-1);
    int x1c = min(max(x1i, 0), W-1);
    float r0 = pool2(rrow, 2*x0c);
    float r1 = pool2(rrow, 2*x1c);
    float warped = (r0 * vv0) * (1.f - frac) + (r1 * vv1) * frac;
    g_featsP[base + (size_t)(9+c) * HW] = bf1(fabsf(l - warped));
}

// interleave two uint2 (4 bf16 each, same x-span, adjacent ci planes) into 4 bf16x2 words
__device__ __forceinline__ uint4 ilv(uint2 a, uint2 b) {
    uint4 o;
    o.x = __byte_perm(a.x, b.x, 0x5410);
    o.y = __byte_perm(a.x, b.x, 0x7632);
    o.z = __byte_perm(a.y, b.y, 0x5410);
    o.w = __byte_perm(a.y, b.y, 0x7632);
    return o;
}

// ================= conv1: 16(pad) -> 32, 3x3, pad 1, BN+ReLU — BF16 MMA =================
__global__ void __launch_bounds__(256, 3) k_conv1(const float* __restrict__ w_unused) {
    __shared__ unsigned int sB[4][8][136];
    int t = threadIdx.x;
    int warp = t >> 5, lane = t & 31;
    int nw = warp;
    int g = lane >> 2, t4 = lane & 3;

    int x0 = blockIdx.x * 128;
    int y0 = blockIdx.y * 2;
    int n  = blockIdx.z;

    float c[2][2][2][4];
    #pragma unroll
    for (int m = 0; m < 2; m++)
        #pragma unroll
        for (int r = 0; r < 2; r++)
            #pragma unroll
            for (int nt = 0; nt < 2; nt++) { c[m][r][nt][0]=0.f; c[m][r][nt][1]=0.f; c[m][r][nt][2]=0.f; c[m][r][nt][3]=0.f; }

    for (int i = t; i < 4*8*34; i += 256) {
        int row = i / 272; int rem = i - row*272;
        int j = rem / 34, xg = rem - j*34;
        int gy = y0 + row - 1, gx0 = x0 - 4 + xg*4;
        uint2 av = make_uint2(0u, 0u), bv = make_uint2(0u, 0u);
        if ((unsigned)gy < H && gx0 >= 0 && gx0 + 3 < W) {
            size_t o = (size_t)gy * W + gx0;
            av = *reinterpret_cast<const uint2*>(&g_featsP[((size_t)(n*16 + 2*j)) * HW + o]);
            bv = *reinterpret_cast<const uint2*>(&g_featsP[((size_t)(n*16 + 2*j + 1)) * HW + o]);
        }
        *reinterpret_cast<uint4*>(&sB[row][j][xg*4]) = ilv(av, bv);
    }
    __syncthreads();

    #pragma unroll
    for (int ky = 0; ky < 3; ky++) {
        #pragma unroll
        for (int kx = 0; kx < 3; kx++) {
            int p = ky*3 + kx;
            uint4 wa[2];
            #pragma unroll
            for (int m = 0; m < 2; m++)
                wa[m] = g_wt1[(m*9 + p)*32 + lane];
            #pragma unroll
            for (int r = 0; r < 2; r++) {
                const unsigned int* bb = &sB[ky + r][t4][nw*16 + g + kx + 3];
                #pragma unroll
                for (int nt = 0; nt < 2; nt++) {
                    unsigned int b0 = bb[nt*8];
                    unsigned int b1 = bb[nt*8 + 4*136];
                    #pragma unroll
                    for (int m = 0; m < 2; m++) {
                        asm volatile(
                            "mma.sync.aligned.m16n8k16.row.col.f32.bf16.bf16.f32 "
                            "{%0,%1,%2,%3}, {%4,%5,%6,%7}, {%8,%9}, {%0,%1,%2,%3};\n"
                            : "+f"(c[m][r][nt][0]), "+f"(c[m][r][nt][1]), "+f"(c[m][r][nt][2]), "+f"(c[m][r][nt][3])
                            : "r"(wa[m].x), "r"(wa[m].y), "r"(wa[m].z), "r"(wa[m].w), "r"(b0), "r"(b1));
                    }
                }
            }
        }
    }

    #pragma unroll
    for (int m = 0; m < 2; m++) {
        int co0 = m*16 + g;
        int co1 = co0 + 8;
        float s0 = g_s1[co0], bo0 = g_bb1[co0];
        float s1 = g_s1[co1], bo1 = g_bb1[co1];
        #pragma unroll
        for (int r = 0; r < 2; r++) {
            #pragma unroll
            for (int nt = 0; nt < 2; nt++) {
                int x = x0 + nw*16 + nt*8 + 2*t4;
                unsigned int o0 = bf2(fmaxf(fmaf(c[m][r][nt][0], s0, bo0), 0.f),
                                      fmaxf(fmaf(c[m][r][nt][1], s0, bo0), 0.f));
                unsigned int o1 = bf2(fmaxf(fmaf(c[m][r][nt][2], s1, bo1), 0.f),
                                      fmaxf(fmaf(c[m][r][nt][3], s1, bo1), 0.f));
                *reinterpret_cast<unsigned int*>(&g_x1[((size_t)(n*32 + co0) * H + y0 + r) * W + x]) = o0;
                *reinterpret_cast<unsigned int*>(&g_x1[((size_t)(n*32 + co1) * H + y0 + r) * W + x]) = o1;
            }
        }
    }
}

// ================= conv2: 32 -> 64, 3x3, pad 1, BN+ReLU — BF16 MMA, pair-packed output =================
// R13 mapping: tile 64co x 64px x 2 rows, 2 M-groups x 4 N-warps x 16 px.
__global__ void __launch_bounds__(256, 3) k_conv2(const float* __restrict__ w_unused) {
    __shared__ unsigned int sB[4][16][72];   // 18.4 KB
    int t = threadIdx.x;
    int warp = t >> 5, lane = t & 31;
    int mg = warp & 1;
    int nw = warp >> 1;
    int g = lane >> 2, t4 = lane & 3;

    int x0 = blockIdx.x * 64;
    int y0 = blockIdx.y * 2;
    int n  = blockIdx.z;

    float c[2][2][2][4];
    #pragma unroll
    for (int m = 0; m < 2; m++)
        #pragma unroll
        for (int r = 0; r < 2; r++)
            #pragma unroll
            for (int nt = 0; nt < 2; nt++) { c[m][r][nt][0]=0.f; c[m][r][nt][1]=0.f; c[m][r][nt][2]=0.f; c[m][r][nt][3]=0.f; }

    for (int i = t; i < 4*16*18; i += 256) {
        int row = i / 288; int rem = i - row*288;
        int j = rem / 18, xg = rem - j*18;
        int gy = y0 + row - 1, gx0 = x0 - 4 + xg*4;
        uint2 av = make_uint2(0u, 0u), bv = make_uint2(0u, 0u);
        if ((unsigned)gy < H && gx0 >= 0 && gx0 + 3 < W) {
            size_t o = (size_t)gy * W + gx0;
            av = *reinterpret_cast<const uint2*>(&g_x1[((size_t)(n*32 + 2*j)) * HW + o]);
            bv = *reinterpret_cast<const uint2*>(&g_x1[((size_t)(n*32 + 2*j + 1)) * HW + o]);
        }
        *reinterpret_cast<uint4*>(&sB[row][j][xg*4]) = ilv(av, bv);
    }
    __syncthreads();

    #pragma unroll
    for (int cc = 0; cc < 2; cc++) {
        #pragma unroll
        for (int ky = 0; ky < 3; ky++) {
            #pragma unroll
            for (int kx = 0; kx < 3; kx++) {
                int p = ky*3 + kx;
                uint4 wa[2];
                #pragma unroll
                for (int m = 0; m < 2; m++)
                    wa[m] = g_wt2[(((mg*2 + m)*9 + p)*2 + cc)*32 + lane];
                #pragma unroll
                for (int r = 0; r < 2; r++) {
                    const unsigned int* bb = &sB[ky + r][cc*8 + t4][nw*16 + g + kx + 3];
                    #pragma unroll
                    for (int nt = 0; nt < 2; nt++) {
                        unsigned int b0 = bb[nt*8];
                        unsigned int b1 = bb[nt*8 + 4*72];
                        #pragma unroll
                        for (int m = 0; m < 2; m++) {
                            asm volatile(
                                "mma.sync.aligned.m16n8k16.row.col.f32.bf16.bf16.f32 "
                                "{%0,%1,%2,%3}, {%4,%5,%6,%7}, {%8,%9}, {%0,%1,%2,%3};\n"
                                : "+f"(c[m][r][nt][0]), "+f"(c[m][r][nt][1]), "+f"(c[m][r][nt][2]), "+f"(c[m][r][nt][3])
                                : "r"(wa[m].x), "r"(wa[m].y), "r"(wa[m].z), "r"(wa[m].w), "r"(b0), "r"(b1));
                        }
                    }
                }
            }
        }
    }

    // epilogue: pair-packed layout — word(px) = bf16x2(co chunk*16+g, co chunk*16+g+8)
    #pragma unroll
    for (int m = 0; m < 2; m++) {
        int chunk = mg*2 + m;
        int co0 = chunk*16 + g;
        int co1 = co0 + 8;
        float s0 = g_s2[co0], bo0 = g_bb2[co0];
        float s1 = g_s2[co1], bo1 = g_bb2[co1];
        unsigned int* plane = g_x2p + ((size_t)(n*4 + chunk)*8 + g) * HW;
        #pragma unroll
        for (int r = 0; r < 2; r++) {
            #pragma unroll
            for (int nt = 0; nt < 2; nt++) {
                int x = x0 + nw*16 + nt*8 + 2*t4;   // even -> 8B-aligned uint2
                unsigned int w0 = bf2(fmaxf(fmaf(c[m][r][nt][0], s0, bo0), 0.f),
                                      fmaxf(fmaf(c[m][r][nt][2], s1, bo1), 0.f));
                unsigned int w1 = bf2(fmaxf(fmaf(c[m][r][nt][1], s0, bo0), 0.f),
                                      fmaxf(fmaf(c[m][r][nt][3], s1, bo1), 0.f));
                *reinterpret_cast<uint2*>(&plane[(size_t)(y0 + r) * W + x]) = make_uint2(w0, w1);
            }
        }
    }
}

// ======== fused tail: conv3 via BF16 MMA on pair-packed x2 + softmax prop ========
__global__ void __launch_bounds__(256) k_tail(const float* __restrict__ disp,
                                              float* __restrict__ out) {
    __shared__ float sAff[8][18][72];   // 40.5 KB
    __shared__ float sD[18][72];        //  5.1 KB
    int t = threadIdx.x;
    int warp = t >> 5, lane = t & 31;
    int g = lane >> 2, t4 = lane & 3;
    int x0 = blockIdx.x * 64;
    int y0 = blockIdx.y * 16;
    int n  = blockIdx.z;

    uint4 wa[4];
    #pragma unroll
    for (int cc = 0; cc < 4; cc++) wa[cc] = g_wt3[cc*32 + lane];

    for (int task = t; task < 18*18; task += 256) {
        int yy = task / 18, jg = task - yy*18;
        int gy = y0 + yy - 1, gx0 = x0 - 4 + jg*4;
        float4 dv = make_float4(0.f, 0.f, 0.f, 0.f);
        if ((unsigned)gy < H && gx0 >= 0 && gx0 + 3 < W)
            dv = *reinterpret_cast<const float4*>(&disp[(size_t)n * HW + (size_t)gy * W + gx0]);
        *reinterpret_cast<float4*>(&sD[yy][jg*4]) = dv;
    }

    // conv3 via MMA on pair-packed words: b0 = word[cc][t4][px], b1 = word[cc][t4+4][px]
    const unsigned int* xb = g_x2p + (size_t)n * 32 * HW;
    for (int grp = warp; grp < 162; grp += 8) {
        int yy = grp / 9, gi = grp - yy*9;
        int gy = y0 + yy - 1;
        int px = x0 - 4 + gi*8 + g;
        bool ok = ((unsigned)gy < H) && ((unsigned)px < W);
        size_t o = ok ? ((size_t)gy * W + px) : 0;
        float c0 = 0.f, c1 = 0.f, c2 = 0.f, c3 = 0.f;
        #pragma unroll
        for (int cc = 0; cc < 4; cc++) {
            unsigned int b0 = ok ? xb[(size_t)(cc*8 + t4)     * HW + o] : 0u;
            unsigned int b1 = ok ? xb[(size_t)(cc*8 + t4 + 4) * HW + o] : 0u;
            asm volatile(
                "mma.sync.aligned.m16n8k16.row.col.f32.bf16.bf16.f32 "
                "{%0,%1,%2,%3}, {%4,%5,%6,%7}, {%8,%9}, {%0,%1,%2,%3};\n"
                : "+f"(c0), "+f"(c1), "+f"(c2), "+f"(c3)
                : "r"(wa[cc].x), "r"(wa[cc].y), "r"(wa[cc].z), "r"(wa[cc].w), "r"(b0), "r"(b1));
        }
        sAff[g][yy][gi*8 + 2*t4]     = fmaxf(c0, 0.f);
        sAff[g][yy][gi*8 + 2*t4 + 1] = fmaxf(c1, 0.f);
    }
    __syncthreads();

    const int dy[8] = { 1, 1, 1, 0, 0, -1, -1, -1 };
    const int dx[8] = { 1, 0,-1, 1,-1,  1,  0, -1 };
    for (int o = t; o < 64*16; o += 256) {
        int oy = o >> 6, ox = o & 63;
        int yy = oy + 1, xx = ox + 4;
        float gg[8], dd[8];
        #pragma unroll
        for (int k = 0; k < 8; k++) {
            gg[k] = sAff[k][yy + dy[k]][xx + dx[k]];
            dd[k] = sD[yy + dy[k]][xx + dx[k]];
        }
        float m = gg[0];
        #pragma unroll
        for (int k = 1; k < 8; k++) m = fmaxf(m, gg[k]);
        float se = 0.f, sp = 0.f;
        #pragma unroll
        for (int k = 0; k < 8; k++) {
            float e = expf(gg[k] - m);
            se += e;
            sp = fmaf(e, dd[k], sp);
        }
        float prop = sp / se;
        out[(size_t)n * HW + (size_t)(y0 + oy) * W + x0 + ox] = 0.3f * prop + 0.7f * sD[yy][xx];
    }
}

// ---------------- launch ----------------
extern "C" void kernel_launch(void* const* d_in, const int* in_sizes, int n_in,
                              void* d_out, int out_size) {
    const float* normal = (const float*)d_in[0];
    const float* left   = (const float*)d_in[1];
    const float* right  = (const float*)d_in[2];
    const float* disp   = (const float*)d_in[3];
    const float* w1 = (const float*)d_in[4];
    const float* g1 = (const float*)d_in[5];
    const float* b1 = (const float*)d_in[6];
    const float* m1 = (const float*)d_in[7];
    const float* v1 = (const float*)d_in[8];
    const float* w2 = (const float*)d_in[9];
    const float* g2 = (const float*)d_in[10];
    const float* b2 = (const float*)d_in[11];
    const float* m2 = (const float*)d_in[12];
    const float* v2 = (const float*)d_in[13];
    const float* w3 = (const float*)d_in[14];
    float* out = (float*)d_out;

    // 6144 pre-blocks + 13 setup-blocks, fused
    k_pre<<<6144 + 13, 256>>>(left, right, normal, disp,
                              w1, w2, w3, g1, b1, m1, v1, g2, b2, m2, v2);

    k_conv1<<<dim3(W/128, H/2, NB), 256>>>(w1);
    k_conv2<<<dim3(W/64, H/2, NB), 256>>>(w2);

    k_tail<<<dim3(W/64, H/16, NB), 256>>>(disp, out);
}